// round 1
// baseline (speedup 1.0000x reference)
#include <cuda_runtime.h>
#include <math.h>

#define NBATCH 4
#define NHID   128
#define NCOL   65536
#define NMODE  256

// Scratch (allocation-free rule: device globals)
__device__ __align__(16) float g_y[2 * NBATCH * NHID * NMODE]; // [ri][b][k][m]  (1 MB)
__device__ __align__(16) float g_c[NHID * NMODE];              // [k][m]  c = lin_w@bias + lin_b (128 KB)

__device__ __forceinline__ float gelu_exact(float v) {
    return 0.5f * v * (1.0f + erff(v * 0.70710678118654752440f));
}

// ---------------------------------------------------------------------------
// Kernel A: per-mode GEMM   y[ri][b,k,m] = sum_h x[b,h,m] * w_{ri}[h,k,m]
// grid (8 k-blocks of 16, 8 m-blocks of 32, 2 ri), 128 threads
// ---------------------------------------------------------------------------
__global__ void __launch_bounds__(128) kmodes(const float* __restrict__ x,
                                              const float* __restrict__ wr,
                                              const float* __restrict__ wi) {
    extern __shared__ float xs[];  // [b*128+h][32]  = 64 KB
    const int kb = blockIdx.x, mb = blockIdx.y, ri = blockIdx.z;
    const float* w = ri ? wi : wr;
    const int m0 = mb * 32, k0 = kb * 16;
    const int tid = threadIdx.x;

    // load x tile (coalesced 128B rows)
    for (int i = tid; i < NBATCH * NHID * 8; i += 128) {
        int j4 = i & 7;
        int bh = i >> 3;
        float4 v = *reinterpret_cast<const float4*>(x + (size_t)bh * NCOL + m0 + j4 * 4);
        *reinterpret_cast<float4*>(xs + bh * 32 + j4 * 4) = v;
    }
    __syncthreads();

    const int kl = tid & 15;      // 16 k per CTA
    const int mg = tid >> 4;      // 8 m-quads
    const int k  = k0 + kl;
    const int mm = mg * 4;

    float a0[NBATCH], a1[NBATCH], a2[NBATCH], a3[NBATCH];
#pragma unroll
    for (int b = 0; b < NBATCH; b++) { a0[b]=0.f; a1[b]=0.f; a2[b]=0.f; a3[b]=0.f; }

    const float* wp = w + (size_t)k * NMODE + m0 + mm;   // w[h][k][m], stride h = 128*256
#pragma unroll 4
    for (int h = 0; h < NHID; h++) {
        float4 wv = __ldg(reinterpret_cast<const float4*>(wp + (size_t)h * NHID * NMODE));
#pragma unroll
        for (int b = 0; b < NBATCH; b++) {
            float4 xv = *reinterpret_cast<const float4*>(xs + (b * NHID + h) * 32 + mm);
            a0[b] += xv.x * wv.x;
            a1[b] += xv.y * wv.y;
            a2[b] += xv.z * wv.z;
            a3[b] += xv.w * wv.w;
        }
    }
#pragma unroll
    for (int b = 0; b < NBATCH; b++) {
        float4 v = make_float4(a0[b], a1[b], a2[b], a3[b]);
        *reinterpret_cast<float4*>(&g_y[((ri * NBATCH + b) * NHID + k) * NMODE + m0 + mm]) = v;
    }
}

// ---------------------------------------------------------------------------
// Kernel B (dominant): c[k,n] = sum_h lin_w[k,h]*bias[h,n]
//   n >= 256: out[b,k,n,0] = gelu(c + lin_b[k]) for all 4 b ; out[...,1] = 0
//   n <  256: g_c[k,n] = c + lin_b[k]   (kernel C finishes that region)
// grid 1024 CTAs x 64 columns, 256 threads, 2 CTAs/SM
// ---------------------------------------------------------------------------
__global__ void __launch_bounds__(256, 2) kmain(const float* __restrict__ bias,
                                                const float* __restrict__ lin_w,
                                                const float* __restrict__ lin_b,
                                                float* __restrict__ out) {
    extern __shared__ float sm[];
    float* sW = sm;                  // [k][h], pitch 129 (conflict-free)   128*129
    float* sb = sm + NHID * 129;     // [h][64]                            128*64
    __shared__ float slb[NHID];

    const int tid = threadIdx.x;
    const int n_base = blockIdx.x * 64;

    for (int i = tid; i < NHID * NHID; i += 256) {
        int h = i & 127, k = i >> 7;
        sW[k * 129 + h] = lin_w[i];          // i == k*128 + h
    }
    if (tid < NHID) slb[tid] = lin_b[tid];
    for (int i = tid; i < NHID * 16; i += 256) {     // 2048 float4 loads
        int h = i >> 4, j = i & 15;
        float4 v = *reinterpret_cast<const float4*>(bias + (size_t)h * NCOL + n_base + j * 4);
        *reinterpret_cast<float4*>(sb + h * 64 + j * 4) = v;
    }
    __syncthreads();

    const int kg = tid >> 3;     // 32 k-groups of 4
    const int ng = tid & 7;      // 8 n-groups of 4

#pragma unroll
    for (int c = 0; c < 2; c++) {
        float acc[4][4];
#pragma unroll
        for (int i = 0; i < 4; i++)
#pragma unroll
            for (int j = 0; j < 4; j++) acc[i][j] = 0.f;

        const float* wp = sW + (kg * 4) * 129;
        const float* bp = sb + c * 32 + ng * 4;
#pragma unroll 2
        for (int h = 0; h < NHID; h++) {
            float4 bv = *reinterpret_cast<const float4*>(bp + h * 64);
            float w0 = wp[h];
            float w1 = wp[129 + h];
            float w2 = wp[2 * 129 + h];
            float w3 = wp[3 * 129 + h];
            acc[0][0] += w0 * bv.x; acc[0][1] += w0 * bv.y; acc[0][2] += w0 * bv.z; acc[0][3] += w0 * bv.w;
            acc[1][0] += w1 * bv.x; acc[1][1] += w1 * bv.y; acc[1][2] += w1 * bv.z; acc[1][3] += w1 * bv.w;
            acc[2][0] += w2 * bv.x; acc[2][1] += w2 * bv.y; acc[2][2] += w2 * bv.z; acc[2][3] += w2 * bv.w;
            acc[3][0] += w3 * bv.x; acc[3][1] += w3 * bv.y; acc[3][2] += w3 * bv.z; acc[3][3] += w3 * bv.w;
        }

        const int n0 = n_base + c * 32 + ng * 4;
        if (n0 >= NMODE) {
#pragma unroll
            for (int i = 0; i < 4; i++) {
                int k = kg * 4 + i;
                float lb = slb[k];
                float v0 = gelu_exact(acc[i][0] + lb);
                float v1 = gelu_exact(acc[i][1] + lb);
                float v2 = gelu_exact(acc[i][2] + lb);
                float v3 = gelu_exact(acc[i][3] + lb);
                float4 lo = make_float4(v0, 0.f, v1, 0.f);
                float4 hi = make_float4(v2, 0.f, v3, 0.f);
#pragma unroll
                for (int b = 0; b < NBATCH; b++) {
                    float* op = out + 2 * ((size_t)(b * NHID + k) * NCOL + n0);
                    *reinterpret_cast<float4*>(op)     = lo;
                    *reinterpret_cast<float4*>(op + 4) = hi;
                }
            }
        } else {
#pragma unroll
            for (int i = 0; i < 4; i++) {
                int k = kg * 4 + i;
                float lb = slb[k];
                float4 v = make_float4(acc[i][0] + lb, acc[i][1] + lb,
                                       acc[i][2] + lb, acc[i][3] + lb);
                *reinterpret_cast<float4*>(&g_c[k * NMODE + n0]) = v;
            }
        }
    }
}

// ---------------------------------------------------------------------------
// Kernel C: n < 256 region.
//   t_{r,i}[b,k,n] = sum_h lin_w[k,h] * g_y[ri][b,h,n]
//   out[b,k,n,0] = gelu(t_r + g_c[k,n]);  out[b,k,n,1] = gelu(t_i)
// grid 128 = (8 m-tiles of 32) x (4 b) x (4 k-blocks of 32), 256 threads
// ---------------------------------------------------------------------------
__global__ void __launch_bounds__(256) ksmall(const float* __restrict__ lin_w,
                                              float* __restrict__ out) {
    extern __shared__ float smc[];
    float* sW = smc;               // [32][129]
    float* sy = smc + 32 * 129;    // [ri*128+h][32]
    const int bx = blockIdx.x;
    const int mt = bx & 7, b = (bx >> 3) & 3, kb = bx >> 5;
    const int tid = threadIdx.x;
    const int m0 = mt * 32;

    for (int i = tid; i < 32 * NHID; i += 256) {
        int h = i & 127, r = i >> 7;
        sW[r * 129 + h] = lin_w[(kb * 32 + r) * NHID + h];
    }
    for (int i = tid; i < 2 * NHID * 8; i += 256) {    // 2048 float4
        int j = i & 7;
        int rh = i >> 3;                 // ri*128 + h
        int ri = rh >> 7, h = rh & 127;
        float4 v = *reinterpret_cast<const float4*>(
            &g_y[(((ri * NBATCH + b) * NHID) + h) * NMODE + m0 + j * 4]);
        *reinterpret_cast<float4*>(sy + rh * 32 + j * 4) = v;
    }
    __syncthreads();

    const int kl = tid >> 3;   // 0..31
    const int ng = tid & 7;
    const int k = kb * 32 + kl;

    float ar[4] = {0.f, 0.f, 0.f, 0.f};
    float ai[4] = {0.f, 0.f, 0.f, 0.f};
    const float* wp  = sW + kl * 129;
    const float* yrp = sy + ng * 4;
    const float* yip = sy + NHID * 32 + ng * 4;
#pragma unroll 2
    for (int h = 0; h < NHID; h++) {
        float w = wp[h];
        float4 r4 = *reinterpret_cast<const float4*>(yrp + h * 32);
        float4 i4 = *reinterpret_cast<const float4*>(yip + h * 32);
        ar[0] += w * r4.x; ar[1] += w * r4.y; ar[2] += w * r4.z; ar[3] += w * r4.w;
        ai[0] += w * i4.x; ai[1] += w * i4.y; ai[2] += w * i4.z; ai[3] += w * i4.w;
    }
    const int n0 = m0 + ng * 4;
    float4 cv = *reinterpret_cast<const float4*>(&g_c[k * NMODE + n0]);
    float4 lo = make_float4(gelu_exact(ar[0] + cv.x), gelu_exact(ai[0]),
                            gelu_exact(ar[1] + cv.y), gelu_exact(ai[1]));
    float4 hi = make_float4(gelu_exact(ar[2] + cv.z), gelu_exact(ai[2]),
                            gelu_exact(ar[3] + cv.w), gelu_exact(ai[3]));
    float* op = out + 2 * ((size_t)(b * NHID + k) * NCOL + n0);
    *reinterpret_cast<float4*>(op)     = lo;
    *reinterpret_cast<float4*>(op + 4) = hi;
}

// ---------------------------------------------------------------------------
extern "C" void kernel_launch(void* const* d_in, const int* in_sizes, int n_in,
                              void* d_out, int out_size) {
    const float* x     = (const float*)d_in[0];
    const float* wr    = (const float*)d_in[1];
    const float* wi    = (const float*)d_in[2];
    const float* bias  = (const float*)d_in[3];
    const float* lin_w = (const float*)d_in[4];
    const float* lin_b = (const float*)d_in[5];
    float* out = (float*)d_out;

    (void)in_sizes; (void)n_in; (void)out_size;

    cudaFuncSetAttribute(kmodes, cudaFuncAttributeMaxDynamicSharedMemorySize, 65536);
    cudaFuncSetAttribute(kmain,  cudaFuncAttributeMaxDynamicSharedMemorySize, 98816);
    cudaFuncSetAttribute(ksmall, cudaFuncAttributeMaxDynamicSharedMemorySize, 49280);

    kmodes<<<dim3(8, 8, 2), 128, 65536>>>(x, wr, wi);
    kmain<<<1024, 256, 98816>>>(bias, lin_w, lin_b, out);
    ksmall<<<128, 256, 49280>>>(lin_w, out);
}

// round 2
// speedup vs baseline: 1.8548x; 1.8548x over previous
#include <cuda_runtime.h>
#include <math.h>

#define NBATCH 4
#define NHID   128
#define NCOL   65536
#define NMODE  256

// Scratch (allocation-free rule: device globals)
// h-split partials: [hs][ri][b][k][m]  4*2*4*128*256 floats = 16 MB
__device__ __align__(16) float g_yp[4 * 2 * NBATCH * NHID * NMODE];
__device__ __align__(16) float g_c[NHID * NMODE];   // [k][m]  c = lin_w@bias + lin_b

__device__ __forceinline__ float gelu_exact(float v) {
    return 0.5f * v * (1.0f + erff(v * 0.70710678118654752440f));
}

// ---------------------------------------------------------------------------
// Kernel A: per-mode GEMM, h split 4 ways.
//  g_yp[hs][ri][b][k][m] = sum_{h in chunk} x[b,h,m] * w_{ri}[h,k,m]
// grid (32 = 8 kb * 4 hs, 8 mb, 2 ri), 128 threads.  Pure DRAM stream of w.
// ---------------------------------------------------------------------------
__global__ void __launch_bounds__(128) kmodes(const float* __restrict__ x,
                                              const float* __restrict__ wr,
                                              const float* __restrict__ wi) {
    __shared__ float xs[NBATCH * 32 * 32];    // [b][h(32)][m(32)] 16 KB
    const int kb = blockIdx.x >> 2, hs = blockIdx.x & 3;
    const int mb = blockIdx.y, ri = blockIdx.z;
    const float* w = ri ? wi : wr;
    const int m0 = mb * 32, k0 = kb * 16, h0 = hs * 32;
    const int tid = threadIdx.x;

    // load x chunk (coalesced)
    for (int i = tid; i < NBATCH * 32 * 8; i += 128) {
        int j = i & 7;
        int bh = i >> 3;                 // b*32 + h
        int b = bh >> 5, h = bh & 31;
        float4 v = *reinterpret_cast<const float4*>(
            x + (size_t)(b * NHID + h0 + h) * NCOL + m0 + j * 4);
        *reinterpret_cast<float4*>(xs + bh * 32 + j * 4) = v;
    }
    __syncthreads();

    const int kl = tid & 15;      // 16 k per CTA
    const int mg = tid >> 4;      // 8 m-quads
    const int k  = k0 + kl;
    const int mm = mg * 4;

    float a[NBATCH][4];
#pragma unroll
    for (int b = 0; b < NBATCH; b++)
#pragma unroll
        for (int j = 0; j < 4; j++) a[b][j] = 0.f;

    const float* wp = w + (size_t)h0 * NHID * NMODE + (size_t)k * NMODE + m0 + mm;
#pragma unroll 8
    for (int h = 0; h < 32; h++) {
        float4 wv = __ldg(reinterpret_cast<const float4*>(wp + (size_t)h * NHID * NMODE));
#pragma unroll
        for (int b = 0; b < NBATCH; b++) {
            float4 xv = *reinterpret_cast<const float4*>(xs + (b * 32 + h) * 32 + mm);
            a[b][0] += xv.x * wv.x;
            a[b][1] += xv.y * wv.y;
            a[b][2] += xv.z * wv.z;
            a[b][3] += xv.w * wv.w;
        }
    }
#pragma unroll
    for (int b = 0; b < NBATCH; b++) {
        float4 v = make_float4(a[b][0], a[b][1], a[b][2], a[b][3]);
        *reinterpret_cast<float4*>(
            &g_yp[(((hs * 2 + ri) * NBATCH + b) * NHID + k) * NMODE + m0 + mm]) = v;
    }
}

// ---------------------------------------------------------------------------
// Kernel B (dominant): c[k,n] = sum_h lin_w[k,h]*bias[h,n]
//   n >= 256: out[b,k,n,0] = gelu(c + lin_b[k]) for all 4 b ; out[...,1] = 0
//   n <  256: g_c[k,n] = c + lin_b[k]
// 1024 CTAs x 64 n-cols, 256 threads (16 kt x 16 nt), 8k x 4n per thread,
// w transposed in smem (broadcast float4 loads), 2 CTAs/SM.
// ---------------------------------------------------------------------------
#define WPITCH 132
__global__ void __launch_bounds__(256, 2) kmain(const float* __restrict__ bias,
                                                const float* __restrict__ lin_w,
                                                const float* __restrict__ lin_b,
                                                float* __restrict__ out) {
    extern __shared__ float sm[];
    float* wT = sm;                      // [h][k] pitch 132 : 128*132 floats
    float* sb = sm + NHID * WPITCH;      // [h][64]
    __shared__ float slb[NHID];

    const int tid = threadIdx.x;
    const int n_base = blockIdx.x * 64;

    // stage lin_w transposed
    for (int i = tid; i < NHID * NHID; i += 256) {
        int h = i & 127, k = i >> 7;
        wT[h * WPITCH + k] = lin_w[i];   // i == k*128 + h
    }
    if (tid < NHID) slb[tid] = lin_b[tid];
    // stage bias tile
    for (int i = tid; i < NHID * 16; i += 256) {
        int h = i >> 4, j = i & 15;
        float4 v = *reinterpret_cast<const float4*>(bias + (size_t)h * NCOL + n_base + j * 4);
        *reinterpret_cast<float4*>(sb + h * 64 + j * 4) = v;
    }
    __syncthreads();

    const int kt = tid >> 4;     // 0..15 -> 8 k each
    const int nt = tid & 15;     // 0..15 -> 4 n each

    float acc[8][4];
#pragma unroll
    for (int i = 0; i < 8; i++)
#pragma unroll
        for (int j = 0; j < 4; j++) acc[i][j] = 0.f;

    const float* wp = wT + kt * 8;
    const float* bp = sb + nt * 4;
#pragma unroll 4
    for (int h = 0; h < NHID; h++) {
        float4 bv = *reinterpret_cast<const float4*>(bp + h * 64);
        float4 wa = *reinterpret_cast<const float4*>(wp + h * WPITCH);
        float4 wb = *reinterpret_cast<const float4*>(wp + h * WPITCH + 4);
        acc[0][0] += wa.x * bv.x; acc[0][1] += wa.x * bv.y; acc[0][2] += wa.x * bv.z; acc[0][3] += wa.x * bv.w;
        acc[1][0] += wa.y * bv.x; acc[1][1] += wa.y * bv.y; acc[1][2] += wa.y * bv.z; acc[1][3] += wa.y * bv.w;
        acc[2][0] += wa.z * bv.x; acc[2][1] += wa.z * bv.y; acc[2][2] += wa.z * bv.z; acc[2][3] += wa.z * bv.w;
        acc[3][0] += wa.w * bv.x; acc[3][1] += wa.w * bv.y; acc[3][2] += wa.w * bv.z; acc[3][3] += wa.w * bv.w;
        acc[4][0] += wb.x * bv.x; acc[4][1] += wb.x * bv.y; acc[4][2] += wb.x * bv.z; acc[4][3] += wb.x * bv.w;
        acc[5][0] += wb.y * bv.x; acc[5][1] += wb.y * bv.y; acc[5][2] += wb.y * bv.z; acc[5][3] += wb.y * bv.w;
        acc[6][0] += wb.z * bv.x; acc[6][1] += wb.z * bv.y; acc[6][2] += wb.z * bv.z; acc[6][3] += wb.z * bv.w;
        acc[7][0] += wb.w * bv.x; acc[7][1] += wb.w * bv.y; acc[7][2] += wb.w * bv.z; acc[7][3] += wb.w * bv.w;
    }

    const int n0 = n_base + nt * 4;
    if (n_base >= NMODE) {
#pragma unroll
        for (int i = 0; i < 8; i++) {
            int k = kt * 8 + i;
            float lb = slb[k];
            float v0 = gelu_exact(acc[i][0] + lb);
            float v1 = gelu_exact(acc[i][1] + lb);
            float v2 = gelu_exact(acc[i][2] + lb);
            float v3 = gelu_exact(acc[i][3] + lb);
            float4 lo = make_float4(v0, 0.f, v1, 0.f);
            float4 hi = make_float4(v2, 0.f, v3, 0.f);
#pragma unroll
            for (int b = 0; b < NBATCH; b++) {
                float* op = out + 2 * ((size_t)(b * NHID + k) * NCOL + n0);
                __stcs(reinterpret_cast<float4*>(op), lo);
                __stcs(reinterpret_cast<float4*>(op + 4), hi);
            }
        }
    } else {
#pragma unroll
        for (int i = 0; i < 8; i++) {
            int k = kt * 8 + i;
            float lb = slb[k];
            float4 v = make_float4(acc[i][0] + lb, acc[i][1] + lb,
                                   acc[i][2] + lb, acc[i][3] + lb);
            *reinterpret_cast<float4*>(&g_c[k * NMODE + n0]) = v;
        }
    }
}

// ---------------------------------------------------------------------------
// Kernel C: n < 256 region. Sums the 4 h-partials of g_yp during smem staging.
//   t_{r,i}[b,k,n] = sum_h lin_w[k,h] * y[ri][b,h,n]
//   out[b,k,n,0] = gelu(t_r + g_c[k,n]);  out[b,k,n,1] = gelu(t_i)
// grid 128 = (8 m-tiles of 32) x (4 b) x (4 k-blocks of 32), 256 threads
// ---------------------------------------------------------------------------
__global__ void __launch_bounds__(256) ksmall(const float* __restrict__ lin_w,
                                              float* __restrict__ out) {
    extern __shared__ float smc[];
    float* sW = smc;               // [32][129]
    float* sy = smc + 32 * 129;    // [ri*128+h][32]
    const int bx = blockIdx.x;
    const int mt = bx & 7, b = (bx >> 3) & 3, kb = bx >> 5;
    const int tid = threadIdx.x;
    const int m0 = mt * 32;

    for (int i = tid; i < 32 * NHID; i += 256) {
        int h = i & 127, r = i >> 7;
        sW[r * 129 + h] = lin_w[(kb * 32 + r) * NHID + h];
    }
    for (int i = tid; i < 2 * NHID * 8; i += 256) {
        int j = i & 7;
        int rh = i >> 3;                 // ri*128 + h
        int ri = rh >> 7, h = rh & 127;
        float4 s = make_float4(0.f, 0.f, 0.f, 0.f);
#pragma unroll
        for (int hsp = 0; hsp < 4; hsp++) {
            float4 v = *reinterpret_cast<const float4*>(
                &g_yp[(((hsp * 2 + ri) * NBATCH + b) * NHID + h) * NMODE + m0 + j * 4]);
            s.x += v.x; s.y += v.y; s.z += v.z; s.w += v.w;
        }
        *reinterpret_cast<float4*>(sy + rh * 32 + j * 4) = s;
    }
    __syncthreads();

    const int kl = tid >> 3;   // 0..31
    const int ng = tid & 7;
    const int k = kb * 32 + kl;

    float ar[4] = {0.f, 0.f, 0.f, 0.f};
    float ai[4] = {0.f, 0.f, 0.f, 0.f};
    const float* wp  = sW + kl * 129;
    const float* yrp = sy + ng * 4;
    const float* yip = sy + NHID * 32 + ng * 4;
#pragma unroll 4
    for (int h = 0; h < NHID; h++) {
        float w = wp[h];
        float4 r4 = *reinterpret_cast<const float4*>(yrp + h * 32);
        float4 i4 = *reinterpret_cast<const float4*>(yip + h * 32);
        ar[0] += w * r4.x; ar[1] += w * r4.y; ar[2] += w * r4.z; ar[3] += w * r4.w;
        ai[0] += w * i4.x; ai[1] += w * i4.y; ai[2] += w * i4.z; ai[3] += w * i4.w;
    }
    const int n0 = m0 + ng * 4;
    float4 cv = *reinterpret_cast<const float4*>(&g_c[k * NMODE + n0]);
    float4 lo = make_float4(gelu_exact(ar[0] + cv.x), gelu_exact(ai[0]),
                            gelu_exact(ar[1] + cv.y), gelu_exact(ai[1]));
    float4 hi = make_float4(gelu_exact(ar[2] + cv.z), gelu_exact(ai[2]),
                            gelu_exact(ar[3] + cv.w), gelu_exact(ai[3]));
    float* op = out + 2 * ((size_t)(b * NHID + k) * NCOL + n0);
    *reinterpret_cast<float4*>(op)     = lo;
    *reinterpret_cast<float4*>(op + 4) = hi;
}

// ---------------------------------------------------------------------------
extern "C" void kernel_launch(void* const* d_in, const int* in_sizes, int n_in,
                              void* d_out, int out_size) {
    const float* x     = (const float*)d_in[0];
    const float* wr    = (const float*)d_in[1];
    const float* wi    = (const float*)d_in[2];
    const float* bias  = (const float*)d_in[3];
    const float* lin_w = (const float*)d_in[4];
    const float* lin_b = (const float*)d_in[5];
    float* out = (float*)d_out;

    (void)in_sizes; (void)n_in; (void)out_size;

    const int kmain_smem = (NHID * WPITCH + NHID * 64) * 4;   // 100352 B
    cudaFuncSetAttribute(kmain,  cudaFuncAttributeMaxDynamicSharedMemorySize, kmain_smem);
    cudaFuncSetAttribute(ksmall, cudaFuncAttributeMaxDynamicSharedMemorySize, 49280);

    kmodes<<<dim3(32, 8, 2), 128>>>(x, wr, wi);
    kmain<<<1024, 256, kmain_smem>>>(bias, lin_w, lin_b, out);
    ksmall<<<128, 256, 49280>>>(lin_w, out);
}

// round 3
// speedup vs baseline: 2.0028x; 1.0798x over previous
#include <cuda_runtime.h>
#include <math.h>

#define NBATCH 4
#define NHID   128
#define NCOL   65536
#define NMODE  256
#define NHS    8          // h-split for kmodes

// Scratch (allocation-free rule: device globals)
// h-split partials: [hs][ri][b][k][m]  8*2*4*128*256 floats = 32 MB
__device__ __align__(16) float g_yp[NHS * 2 * NBATCH * NHID * NMODE];
__device__ __align__(16) float g_c[NHID * NMODE];   // [k][m]  c = lin_w@bias + lin_b

__device__ __forceinline__ float gelu_exact(float v) {
    return 0.5f * v * (1.0f + erff(v * 0.70710678118654752440f));
}

// ---- packed f32x2 helpers (SASS FFMA2; PTX-only path on sm_103a) ----------
__device__ __forceinline__ unsigned long long pack2_dup(float v) {
    unsigned long long r;
    unsigned int u = __float_as_uint(v);
    asm("mov.b64 %0, {%1, %1};" : "=l"(r) : "r"(u));
    return r;
}
__device__ __forceinline__ void fma2(unsigned long long& d,
                                     unsigned long long a, unsigned long long b) {
    asm("fma.rn.f32x2 %0, %1, %2, %0;" : "+l"(d) : "l"(a), "l"(b));
}
__device__ __forceinline__ float2 unpack2(unsigned long long v) {
    unsigned int lo, hi;
    asm("mov.b64 {%0, %1}, %2;" : "=r"(lo), "=r"(hi) : "l"(v));
    return make_float2(__uint_as_float(lo), __uint_as_float(hi));
}

// ---------------------------------------------------------------------------
// Kernel A: per-mode GEMM, h split 8 ways (16 h per chunk).
//  g_yp[hs][ri][b][k][m] = sum_{h in chunk} x[b,h,m] * w_{ri}[h,k,m]
// grid (64 = 8 kb * 8 hs, 8 mb, 2 ri) = 1024 CTAs, 128 threads. DRAM stream.
// ---------------------------------------------------------------------------
__global__ void __launch_bounds__(128) kmodes(const float* __restrict__ x,
                                              const float* __restrict__ wr,
                                              const float* __restrict__ wi) {
    __shared__ float xs[NBATCH * 16 * 32];    // 8 KB
    const int kb = blockIdx.x >> 3, hs = blockIdx.x & 7;
    const int mb = blockIdx.y, ri = blockIdx.z;
    const float* w = ri ? wi : wr;
    const int m0 = mb * 32, k0 = kb * 16, h0 = hs * 16;
    const int tid = threadIdx.x;

    for (int i = tid; i < NBATCH * 16 * 8; i += 128) {
        int j = i & 7;
        int bh = i >> 3;                 // b*16 + h
        int b = bh >> 4, h = bh & 15;
        float4 v = *reinterpret_cast<const float4*>(
            x + (size_t)(b * NHID + h0 + h) * NCOL + m0 + j * 4);
        *reinterpret_cast<float4*>(xs + bh * 32 + j * 4) = v;
    }
    __syncthreads();

    const int kl = tid & 15;      // 16 k per CTA
    const int mg = tid >> 4;      // 8 m-quads
    const int k  = k0 + kl;
    const int mm = mg * 4;

    float a[NBATCH][4];
#pragma unroll
    for (int b = 0; b < NBATCH; b++)
#pragma unroll
        for (int j = 0; j < 4; j++) a[b][j] = 0.f;

    const float* wp = w + (size_t)h0 * NHID * NMODE + (size_t)k * NMODE + m0 + mm;
#pragma unroll 8
    for (int h = 0; h < 16; h++) {
        float4 wv = __ldg(reinterpret_cast<const float4*>(wp + (size_t)h * NHID * NMODE));
#pragma unroll
        for (int b = 0; b < NBATCH; b++) {
            float4 xv = *reinterpret_cast<const float4*>(xs + (b * 16 + h) * 32 + mm);
            a[b][0] += xv.x * wv.x;
            a[b][1] += xv.y * wv.y;
            a[b][2] += xv.z * wv.z;
            a[b][3] += xv.w * wv.w;
        }
    }
#pragma unroll
    for (int b = 0; b < NBATCH; b++) {
        float4 v = make_float4(a[b][0], a[b][1], a[b][2], a[b][3]);
        *reinterpret_cast<float4*>(
            &g_yp[(((hs * 2 + ri) * NBATCH + b) * NHID + k) * NMODE + m0 + mm]) = v;
    }
}

// ---------------------------------------------------------------------------
// Kernel B (dominant): c[k,n] = sum_h lin_w[k,h]*bias[h,n]  via FFMA2.
//   n >= 256: out[b,k,n,0] = gelu(c + lin_b[k]) for all 4 b ; out[...,1] = 0
//   n <  256: g_c[k,n] = c + lin_b[k]
// 1024 CTAs x 64 n-cols, 256 threads (16 kt x 16 nt), 8k x 4n per thread.
// Accumulators paired along k so weights load as packed LDS (no movs for w).
// ---------------------------------------------------------------------------
#define WPITCH 132
__global__ void __launch_bounds__(256, 2) kmain(const float* __restrict__ bias,
                                                const float* __restrict__ lin_w,
                                                const float* __restrict__ lin_b,
                                                float* __restrict__ out) {
    extern __shared__ float sm[];
    float* wT = sm;                      // [h][k] pitch 132 (528B rows, 16B-aligned)
    float* sb = sm + NHID * WPITCH;      // [h][64]
    __shared__ float slb[NHID];

    const int tid = threadIdx.x;
    const int n_base = blockIdx.x * 64;

    for (int i = tid; i < NHID * NHID; i += 256) {
        int h = i & 127, k = i >> 7;
        wT[h * WPITCH + k] = lin_w[i];   // i == k*128 + h
    }
    if (tid < NHID) slb[tid] = lin_b[tid];
    for (int i = tid; i < NHID * 16; i += 256) {
        int h = i >> 4, j = i & 15;
        float4 v = *reinterpret_cast<const float4*>(bias + (size_t)h * NCOL + n_base + j * 4);
        *reinterpret_cast<float4*>(sb + h * 64 + j * 4) = v;
    }
    __syncthreads();

    const int kt = tid >> 4;     // 0..15 -> 8 k each (4 packed pairs)
    const int nt = tid & 15;     // 0..15 -> 4 n each

    unsigned long long acc2[4][4];   // [k-pair][n]
#pragma unroll
    for (int p = 0; p < 4; p++)
#pragma unroll
        for (int j = 0; j < 4; j++) acc2[p][j] = 0ULL;

    const float* wrow = wT + kt * 8;
    const float* bp = sb + nt * 4;
#pragma unroll 4
    for (int h = 0; h < NHID; h++) {
        float4 bv = *reinterpret_cast<const float4*>(bp + h * 64);
        ulonglong2 wA = *reinterpret_cast<const ulonglong2*>(wrow + h * WPITCH);
        ulonglong2 wB = *reinterpret_cast<const ulonglong2*>(wrow + h * WPITCH + 4);
        unsigned long long bn0 = pack2_dup(bv.x);
        unsigned long long bn1 = pack2_dup(bv.y);
        unsigned long long bn2 = pack2_dup(bv.z);
        unsigned long long bn3 = pack2_dup(bv.w);
        fma2(acc2[0][0], wA.x, bn0); fma2(acc2[0][1], wA.x, bn1);
        fma2(acc2[0][2], wA.x, bn2); fma2(acc2[0][3], wA.x, bn3);
        fma2(acc2[1][0], wA.y, bn0); fma2(acc2[1][1], wA.y, bn1);
        fma2(acc2[1][2], wA.y, bn2); fma2(acc2[1][3], wA.y, bn3);
        fma2(acc2[2][0], wB.x, bn0); fma2(acc2[2][1], wB.x, bn1);
        fma2(acc2[2][2], wB.x, bn2); fma2(acc2[2][3], wB.x, bn3);
        fma2(acc2[3][0], wB.y, bn0); fma2(acc2[3][1], wB.y, bn1);
        fma2(acc2[3][2], wB.y, bn2); fma2(acc2[3][3], wB.y, bn3);
    }

    const int n0 = n_base + nt * 4;
    if (n_base >= NMODE) {
#pragma unroll
        for (int p = 0; p < 4; p++) {
            int k0 = kt * 8 + 2 * p;
            float lb0 = slb[k0], lb1 = slb[k0 + 1];
            float2 a0 = unpack2(acc2[p][0]);
            float2 a1 = unpack2(acc2[p][1]);
            float2 a2 = unpack2(acc2[p][2]);
            float2 a3 = unpack2(acc2[p][3]);
            float4 lo0 = make_float4(gelu_exact(a0.x + lb0), 0.f, gelu_exact(a1.x + lb0), 0.f);
            float4 hi0 = make_float4(gelu_exact(a2.x + lb0), 0.f, gelu_exact(a3.x + lb0), 0.f);
            float4 lo1 = make_float4(gelu_exact(a0.y + lb1), 0.f, gelu_exact(a1.y + lb1), 0.f);
            float4 hi1 = make_float4(gelu_exact(a2.y + lb1), 0.f, gelu_exact(a3.y + lb1), 0.f);
#pragma unroll
            for (int b = 0; b < NBATCH; b++) {
                float* op0 = out + 2 * ((size_t)(b * NHID + k0) * NCOL + n0);
                float* op1 = op0 + 2 * NCOL;
                __stcs(reinterpret_cast<float4*>(op0),     lo0);
                __stcs(reinterpret_cast<float4*>(op0 + 4), hi0);
                __stcs(reinterpret_cast<float4*>(op1),     lo1);
                __stcs(reinterpret_cast<float4*>(op1 + 4), hi1);
            }
        }
    } else {
#pragma unroll
        for (int p = 0; p < 4; p++) {
            int k0 = kt * 8 + 2 * p;
            float lb0 = slb[k0], lb1 = slb[k0 + 1];
            float2 a0 = unpack2(acc2[p][0]);
            float2 a1 = unpack2(acc2[p][1]);
            float2 a2 = unpack2(acc2[p][2]);
            float2 a3 = unpack2(acc2[p][3]);
            *reinterpret_cast<float4*>(&g_c[k0 * NMODE + n0]) =
                make_float4(a0.x + lb0, a1.x + lb0, a2.x + lb0, a3.x + lb0);
            *reinterpret_cast<float4*>(&g_c[(k0 + 1) * NMODE + n0]) =
                make_float4(a0.y + lb1, a1.y + lb1, a2.y + lb1, a3.y + lb1);
        }
    }
}

// ---------------------------------------------------------------------------
// Kernel C: n < 256 region. Sums the 8 h-partials of g_yp during smem staging.
//   out[b,k,n,0] = gelu(sum_h lin_w[k,h]*y_r + g_c[k,n]); out[...,1] = gelu(..y_i)
// grid 128 = (8 m-tiles of 32) x (4 b) x (4 k-blocks of 32), 256 threads
// ---------------------------------------------------------------------------
__global__ void __launch_bounds__(256) ksmall(const float* __restrict__ lin_w,
                                              float* __restrict__ out) {
    extern __shared__ float smc[];
    float* sW = smc;               // [32][129]
    float* sy = smc + 32 * 129;    // [ri*128+h][32]
    const int bx = blockIdx.x;
    const int mt = bx & 7, b = (bx >> 3) & 3, kb = bx >> 5;
    const int tid = threadIdx.x;
    const int m0 = mt * 32;

    for (int i = tid; i < 32 * NHID; i += 256) {
        int h = i & 127, r = i >> 7;
        sW[r * 129 + h] = lin_w[(kb * 32 + r) * NHID + h];
    }
    for (int i = tid; i < 2 * NHID * 8; i += 256) {
        int j = i & 7;
        int rh = i >> 3;                 // ri*128 + h
        int ri = rh >> 7, h = rh & 127;
        float4 s = make_float4(0.f, 0.f, 0.f, 0.f);
#pragma unroll
        for (int hsp = 0; hsp < NHS; hsp++) {
            float4 v = *reinterpret_cast<const float4*>(
                &g_yp[(((hsp * 2 + ri) * NBATCH + b) * NHID + h) * NMODE + m0 + j * 4]);
            s.x += v.x; s.y += v.y; s.z += v.z; s.w += v.w;
        }
        *reinterpret_cast<float4*>(sy + rh * 32 + j * 4) = s;
    }
    __syncthreads();

    const int kl = tid >> 3;   // 0..31
    const int ng = tid & 7;
    const int k = kb * 32 + kl;

    float ar[4] = {0.f, 0.f, 0.f, 0.f};
    float ai[4] = {0.f, 0.f, 0.f, 0.f};
    const float* wp  = sW + kl * 129;
    const float* yrp = sy + ng * 4;
    const float* yip = sy + NHID * 32 + ng * 4;
#pragma unroll 4
    for (int h = 0; h < NHID; h++) {
        float w = wp[h];
        float4 r4 = *reinterpret_cast<const float4*>(yrp + h * 32);
        float4 i4 = *reinterpret_cast<const float4*>(yip + h * 32);
        ar[0] += w * r4.x; ar[1] += w * r4.y; ar[2] += w * r4.z; ar[3] += w * r4.w;
        ai[0] += w * i4.x; ai[1] += w * i4.y; ai[2] += w * i4.z; ai[3] += w * i4.w;
    }
    const int n0 = m0 + ng * 4;
    float4 cv = *reinterpret_cast<const float4*>(&g_c[k * NMODE + n0]);
    float4 lo = make_float4(gelu_exact(ar[0] + cv.x), gelu_exact(ai[0]),
                            gelu_exact(ar[1] + cv.y), gelu_exact(ai[1]));
    float4 hi = make_float4(gelu_exact(ar[2] + cv.z), gelu_exact(ai[2]),
                            gelu_exact(ar[3] + cv.w), gelu_exact(ai[3]));
    float* op = out + 2 * ((size_t)(b * NHID + k) * NCOL + n0);
    *reinterpret_cast<float4*>(op)     = lo;
    *reinterpret_cast<float4*>(op + 4) = hi;
}

// ---------------------------------------------------------------------------
extern "C" void kernel_launch(void* const* d_in, const int* in_sizes, int n_in,
                              void* d_out, int out_size) {
    const float* x     = (const float*)d_in[0];
    const float* wr    = (const float*)d_in[1];
    const float* wi    = (const float*)d_in[2];
    const float* bias  = (const float*)d_in[3];
    const float* lin_w = (const float*)d_in[4];
    const float* lin_b = (const float*)d_in[5];
    float* out = (float*)d_out;

    (void)in_sizes; (void)n_in; (void)out_size;

    const int kmain_smem = (NHID * WPITCH + NHID * 64) * 4;   // 100352 B
    cudaFuncSetAttribute(kmain,  cudaFuncAttributeMaxDynamicSharedMemorySize, kmain_smem);
    cudaFuncSetAttribute(ksmall, cudaFuncAttributeMaxDynamicSharedMemorySize, 49280);

    kmodes<<<dim3(64, 8, 2), 128>>>(x, wr, wi);
    kmain<<<1024, 256, kmain_smem>>>(bias, lin_w, lin_b, out);
    ksmall<<<128, 256, 49280>>>(lin_w, out);
}